// round 6
// baseline (speedup 1.0000x reference)
#include <cuda_runtime.h>

#define H_IN   161
#define W_IN   161
#define C      128
#define H_OUT  641
#define W_OUT  641
#define NPIX   (H_OUT * W_OUT)
#define NEGV   (-1000000000.0f)

// Per-slot classification results (phase A -> phase B)
__device__ int      g_maskid[128];   // det_subset_index (cumsum(detected)-1)
__device__ int      g_sem[128];      // cls_pred (argmax class)
__device__ unsigned g_detmask[4];    // 128-bit detected mask
__device__ int      g_hasdet;

// ---------------------------------------------------------------------------
// Phase A: per-slot argmax/max over 133 classes, detection mask, cumsum.
// 1 block, 128 threads. Tiny.
// ---------------------------------------------------------------------------
__global__ void classify_kernel(const float* __restrict__ probs /*128x134*/) {
    __shared__ unsigned char sdet[128];
    int s = threadIdx.x;
    const float* row = probs + s * 134;
    float best = row[0];
    int bi = 0;
    for (int c = 1; c < 133; ++c) {
        float v = row[c];
        if (v > best) { best = v; bi = c; }   // strict > keeps first occurrence
    }
    g_sem[s] = bi;
    sdet[s] = (best >= 0.7f) ? 1 : 0;
    __syncthreads();
    if (s == 0) {
        int cum = 0;
        unsigned m[4] = {0u, 0u, 0u, 0u};
        for (int i = 0; i < 128; ++i) {
            if (sdet[i]) { m[i >> 5] |= 1u << (i & 31); cum++; }
            g_maskid[i] = cum - 1;
        }
        g_detmask[0] = m[0]; g_detmask[1] = m[1];
        g_detmask[2] = m[2]; g_detmask[3] = m[3];
        g_hasdet = (cum > 0) ? 1 : 0;
    }
}

// ---------------------------------------------------------------------------
// Phase B: one block per output row.
//  1) y-interp two input rows into SMEM rowbuf[161][128] (separable bilinear)
//  2) 4-thread quads: each quad owns a group of 4 consecutive output pixels
//     sharing the same (x0, x0+1) column pair. Each thread caches 32 channels
//     of both columns in registers, then for each sub-pixel does x-lerp,
//     full-max, detected-max+argmax (first-occurrence ties), and exp-sum.
// ---------------------------------------------------------------------------
extern __shared__ float rowbuf[];   // W_IN * C floats = 82432 bytes

__global__ void __launch_bounds__(256, 2)
postproc_kernel(const float* __restrict__ in, float* __restrict__ out) {
    const int y  = blockIdx.x;
    const int y0 = y >> 2;
    const int y1 = min(y0 + 1, H_IN - 1);
    const float wy   = (float)(y & 3) * 0.25f;
    const float omwy = 1.0f - wy;

    // ---- Phase 1: build y-interpolated row buffer ----
    {
        const float4* r0 = (const float4*)(in + (size_t)y0 * W_IN * C);
        const float4* r1 = (const float4*)(in + (size_t)y1 * W_IN * C);
        float4* rb = (float4*)rowbuf;
        const int NV = W_IN * C / 4;   // 5152
        if (wy == 0.0f) {
            for (int i = threadIdx.x; i < NV; i += 256) rb[i] = r0[i];
        } else {
            for (int i = threadIdx.x; i < NV; i += 256) {
                float4 a = r0[i], b = r1[i], t;
                t.x = a.x * omwy + b.x * wy;
                t.y = a.y * omwy + b.y * wy;
                t.z = a.z * omwy + b.z * wy;
                t.w = a.w * omwy + b.w * wy;
                rb[i] = t;
            }
        }
    }
    __syncthreads();

    const int lane = threadIdx.x & 31;
    const int q    = lane & 3;          // sub-thread in quad -> channel block
    const int c0   = q * 32;            // this thread's channel base
    const unsigned dword = g_detmask[q];
    const int hasdet = g_hasdet;
    const unsigned qmask = 0xFu << (lane & ~3);  // shfl member mask: own quad

    const int quad_global = threadIdx.x >> 2;    // 0..63

    // 161 column-groups: group g covers output x = 4g .. min(4g+3, 640)
    for (int g = quad_global; g <= 160; g += 64) {
        const int x0 = g;
        const int x1 = min(g + 1, W_IN - 1);

        float a[32], b[32];
        {
            const float4* pa = (const float4*)(rowbuf + x0 * C + c0);
            const float4* pb = (const float4*)(rowbuf + x1 * C + c0);
            #pragma unroll
            for (int i = 0; i < 8; ++i) {
                float4 va = pa[i];
                a[4*i+0] = va.x; a[4*i+1] = va.y; a[4*i+2] = va.z; a[4*i+3] = va.w;
                float4 vb = pb[i];
                b[4*i+0] = vb.x; b[4*i+1] = vb.y; b[4*i+2] = vb.z; b[4*i+3] = vb.w;
            }
        }

        const int nsub = (g == 160) ? 1 : 4;
        for (int sub = 0; sub < nsub; ++sub) {
            const float wx   = (float)sub * 0.25f;
            const float omwx = 1.0f - wx;

            // pass 1: full max + detected max/argmax over this thread's 32 ch
            float fm = -3.402823466e38f;
            float bv = -3.402823466e38f;
            int   bi = c0;
            #pragma unroll
            for (int c = 0; c < 32; ++c) {
                float v  = a[c] * omwx + b[c] * wx;
                fm = fmaxf(fm, v);
                float mv = ((dword >> c) & 1u) ? v : NEGV;
                if (mv > bv) { bv = mv; bi = c0 + c; }   // strict >: first occurrence
            }
            // quad reduction (lanes l^1, l^2 are in the same quad)
            #pragma unroll
            for (int off = 1; off <= 2; off <<= 1) {
                float ofm = __shfl_xor_sync(qmask, fm, off);
                float obv = __shfl_xor_sync(qmask, bv, off);
                int   obi = __shfl_xor_sync(qmask, bi, off);
                fm = fmaxf(fm, ofm);
                if (obv > bv || (obv == bv && obi < bi)) { bv = obv; bi = obi; }
            }

            // pass 2: sum exp(masked - det_max); undetected -> exp(NEG-bv) = 0
            float s = 0.0f;
            #pragma unroll
            for (int c = 0; c < 32; ++c) {
                float v  = a[c] * omwx + b[c] * wx;
                float mv = ((dword >> c) & 1u) ? v : NEGV;
                s += __expf(mv - bv);
            }
            #pragma unroll
            for (int off = 1; off <= 2; off <<= 1)
                s += __shfl_xor_sync(qmask, s, off);

            if (q == 0) {
                const int x = 4 * g + sub;
                const int p = y * W_OUT + x;
                float maskid, sem, thing, stuff;
                if (hasdet) {
                    // pixel_conf > 0.4  <=>  1/s > 0.4  <=>  s < 2.5
                    float cf = (s < 2.5f && fm == bv) ? 1.0f : 0.0f;
                    int semI = g_sem[bi];
                    maskid = (float)(g_maskid[bi] + 1);
                    sem    = (float)semI;              // THING_STUFF_IDS == identity
                    thing  = (semI < 80)  ? cf : 0.0f;
                    stuff  = (semI >= 80) ? cf : 0.0f;
                } else {
                    maskid = 1.0f; sem = 0.0f; thing = 0.0f; stuff = 0.0f;
                }
                out[p]            = maskid;
                out[NPIX + p]     = sem;
                out[2 * NPIX + p] = thing;
                out[3 * NPIX + p] = stuff;
            }
        }
    }
}

// ---------------------------------------------------------------------------
extern "C" void kernel_launch(void* const* d_in, const int* in_sizes, int n_in,
                              void* d_out, int out_size) {
    const float* logits = (const float*)d_in[0];  // (161,161,128)
    const float* probs  = (const float*)d_in[1];  // (128,134)
    if (n_in >= 2 && in_sizes[0] < in_sizes[1]) { // safety: order by size
        const float* t = logits; logits = probs; probs = t;
    }
    float* out = (float*)d_out;

    static int smem_set = 0;
    const int smem_bytes = W_IN * C * sizeof(float);  // 82432
    if (!smem_set) {
        cudaFuncSetAttribute(postproc_kernel,
                             cudaFuncAttributeMaxDynamicSharedMemorySize,
                             smem_bytes);
        smem_set = 1;
    }

    classify_kernel<<<1, 128>>>(probs);
    postproc_kernel<<<H_OUT, 256, smem_bytes>>>(logits, out);
}

// round 7
// speedup vs baseline: 1.3738x; 1.3738x over previous
#include <cuda_runtime.h>

#define H_IN   161
#define W_IN   161
#define C      128
#define H_OUT  641
#define W_OUT  641
#define NPIX   (H_OUT * W_OUT)
#define NEGV   (-1000000000.0f)
#define LOG2E  1.4426950408889634f

// Per-slot classification results (phase A -> phase B)
__device__ int      g_maskid[128];   // det_subset_index (cumsum(detected)-1)
__device__ int      g_sem[128];      // cls_pred (argmax class)
__device__ unsigned g_detmask[4];    // 128-bit detected mask
__device__ int      g_hasdet;

// ---------------------------------------------------------------------------
// Phase A: per-slot argmax/max over 133 classes, detection mask, cumsum.
// ---------------------------------------------------------------------------
__global__ void classify_kernel(const float* __restrict__ probs /*128x134*/) {
    __shared__ unsigned char sdet[128];
    int s = threadIdx.x;
    const float* row = probs + s * 134;
    float best = row[0];
    int bi = 0;
    for (int c = 1; c < 133; ++c) {
        float v = row[c];
        if (v > best) { best = v; bi = c; }   // strict > keeps first occurrence
    }
    g_sem[s] = bi;
    sdet[s] = (best >= 0.7f) ? 1 : 0;
    __syncthreads();
    if (s == 0) {
        int cum = 0;
        unsigned m[4] = {0u, 0u, 0u, 0u};
        for (int i = 0; i < 128; ++i) {
            if (sdet[i]) { m[i >> 5] |= 1u << (i & 31); cum++; }
            g_maskid[i] = cum - 1;
        }
        g_detmask[0] = m[0]; g_detmask[1] = m[1];
        g_detmask[2] = m[2]; g_detmask[3] = m[3];
        g_hasdet = (cum > 0) ? 1 : 0;
    }
}

// ---------------------------------------------------------------------------
// Phase B: grid (3, 641). Each block handles one 256-pixel segment of one
// output row. SMEM holds the y-interpolated (and log2e-prescaled) input
// columns this segment needs (<=65 cols, stride 132 to avoid bank conflicts)
// plus a 128-entry detection bias array (0 or -1e9).
// Thread-per-pixel: fused single pass over 128 channels computes
// full-max, detected-max + first-occurrence argmax, and sum of 2^masked.
// ---------------------------------------------------------------------------
#define NCOLS   65
#define STRIDE  132
#define EX2(dst, src) asm("ex2.approx.f32 %0, %1;" : "=f"(dst) : "f"(src))

__global__ void __launch_bounds__(256, 4)
postproc_kernel(const float* __restrict__ in, float* __restrict__ out) {
    __shared__ float sbuf[NCOLS * STRIDE];   // 34320 B
    __shared__ float sbias[128];

    const int y  = blockIdx.y;
    const int y0 = y >> 2;
    const int y1 = min(y0 + 1, H_IN - 1);
    const float wy = (float)(y & 3) * 0.25f;
    const float w1 = wy * LOG2E;
    const float w0 = (1.0f - wy) * LOG2E;

    const int cb = blockIdx.x * 64;            // base input column: 0 / 64 / 128
    const int nc = min(NCOLS, W_IN - cb);      // 65 / 65 / 33

    // ---- fill: y-lerp (prescaled by log2e) into SMEM ----
    {
        const float4* r0 = (const float4*)(in + ((size_t)y0 * W_IN + cb) * C);
        const float4* r1 = (const float4*)(in + ((size_t)y1 * W_IN + cb) * C);
        const int nv = nc * 32;                // float4s
        for (int i = threadIdx.x; i < nv; i += 256) {
            const int col = i >> 5, j = i & 31;
            float4 a = r0[col * 32 + j];
            float4 b = r1[col * 32 + j];
            float4 t;
            t.x = a.x * w0 + b.x * w1;
            t.y = a.y * w0 + b.y * w1;
            t.z = a.z * w0 + b.z * w1;
            t.w = a.w * w0 + b.w * w1;
            *(float4*)(sbuf + col * STRIDE + j * 4) = t;
        }
        if (threadIdx.x < 128) {
            unsigned m = g_detmask[threadIdx.x >> 5];
            sbias[threadIdx.x] = ((m >> (threadIdx.x & 31)) & 1u) ? 0.0f : NEGV;
        }
    }
    __syncthreads();

    const int px = cb * 4 + threadIdx.x;       // output x of this thread
    if (px >= W_OUT) return;

    const int x0 = px >> 2;
    const int x1 = min(x0 + 1, W_IN - 1);
    const float wx   = (float)(px & 3) * 0.25f;
    const float omwx = 1.0f - wx;

    const float4* pa = (const float4*)(sbuf + (x0 - cb) * STRIDE);
    const float4* pb = (const float4*)(sbuf + (x1 - cb) * STRIDE);
    const float4* pg = (const float4*)sbias;

    float fm = -3.402823466e38f;   // full max (log2-scaled domain)
    float bv = -3.402823466e38f;   // detected max
    float s  = 0.0f;               // sum of 2^(masked)
    int   bi = 0;

    #pragma unroll
    for (int c4 = 0; c4 < 32; ++c4) {
        const float4 A = pa[c4];
        const float4 B = pb[c4];
        const float4 G = pg[c4];   // broadcast
        {
            float v = A.x * omwx + B.x * wx;
            fm = fmaxf(fm, v);
            float mv = v + G.x;
            if (mv > bv) { bv = mv; bi = 4 * c4 + 0; }
            float e; EX2(e, mv); s += e;
        }
        {
            float v = A.y * omwx + B.y * wx;
            fm = fmaxf(fm, v);
            float mv = v + G.y;
            if (mv > bv) { bv = mv; bi = 4 * c4 + 1; }
            float e; EX2(e, mv); s += e;
        }
        {
            float v = A.z * omwx + B.z * wx;
            fm = fmaxf(fm, v);
            float mv = v + G.z;
            if (mv > bv) { bv = mv; bi = 4 * c4 + 2; }
            float e; EX2(e, mv); s += e;
        }
        {
            float v = A.w * omwx + B.w * wx;
            fm = fmaxf(fm, v);
            float mv = v + G.w;
            if (mv > bv) { bv = mv; bi = 4 * c4 + 3; }
            float e; EX2(e, mv); s += e;
        }
    }

    // epilogue: pixel_conf > 0.4  <=>  s < 2.5 * 2^bv
    float eb; EX2(eb, bv);
    const float cf = (s < 2.5f * eb && fm == bv) ? 1.0f : 0.0f;

    float maskid, sem, thing, stuff;
    if (g_hasdet) {
        const int semI = g_sem[bi];
        maskid = (float)(g_maskid[bi] + 1);
        sem    = (float)semI;                 // THING_STUFF_IDS == identity
        thing  = (semI < 80)  ? cf : 0.0f;
        stuff  = (semI >= 80) ? cf : 0.0f;
    } else {
        maskid = 1.0f; sem = 0.0f; thing = 0.0f; stuff = 0.0f;
    }

    const int p = y * W_OUT + px;
    out[p]            = maskid;
    out[NPIX + p]     = sem;
    out[2 * NPIX + p] = thing;
    out[3 * NPIX + p] = stuff;
}

// ---------------------------------------------------------------------------
extern "C" void kernel_launch(void* const* d_in, const int* in_sizes, int n_in,
                              void* d_out, int out_size) {
    const float* logits = (const float*)d_in[0];  // (161,161,128)
    const float* probs  = (const float*)d_in[1];  // (128,134)
    if (n_in >= 2 && in_sizes[0] < in_sizes[1]) { // safety: order by size
        const float* t = logits; logits = probs; probs = t;
    }
    float* out = (float*)d_out;

    classify_kernel<<<1, 128>>>(probs);
    postproc_kernel<<<dim3(3, H_OUT), 256>>>(logits, out);
}

// round 8
// speedup vs baseline: 2.5234x; 1.8368x over previous
#include <cuda_runtime.h>
#include <float.h>

#define H_IN   161
#define W_IN   161
#define C      128
#define H_OUT  641
#define W_OUT  641
#define NPIX   (H_OUT * W_OUT)
#define NEGV   (-1000000000.0f)
#define LOG2E  1.4426950408889634f

typedef unsigned long long ull;

// Per-slot classification results (phase A -> phase B)
__device__ int      g_maskid[128];   // det_subset_index (cumsum(detected)-1)
__device__ int      g_sem[128];      // cls_pred (argmax class)
__device__ unsigned g_detmask[4];    // 128-bit detected mask
__device__ int      g_hasdet;
__device__ int      g_alldet;        // all 128 slots detected -> fast path

// ---------------------------------------------------------------------------
// Phase A: per-slot argmax/max over 133 classes, ballot-based cumsum.
// ---------------------------------------------------------------------------
__global__ void classify_kernel(const float* __restrict__ probs /*128x134*/) {
    __shared__ unsigned w[4];
    const int s    = threadIdx.x;          // 0..127
    const int lane = s & 31;
    const int wid  = s >> 5;

    const float* row = probs + s * 134;
    float best = row[0];
    int bi = 0;
    for (int c = 1; c < 133; ++c) {
        float v = row[c];
        if (v > best) { best = v; bi = c; }   // strict > keeps first occurrence
    }
    g_sem[s] = bi;

    const bool det = (best >= 0.7f);
    unsigned b = __ballot_sync(0xffffffffu, det);
    if (lane == 0) w[wid] = b;
    __syncthreads();

    // inclusive count of detections up to and including slot s
    int cnt = __popc(b & (0xffffffffu >> (31 - lane)));
    for (int k = 0; k < wid; ++k) cnt += __popc(w[k]);
    g_maskid[s] = cnt - 1;

    if (s == 0) {
        int tot = __popc(w[0]) + __popc(w[1]) + __popc(w[2]) + __popc(w[3]);
        g_detmask[0] = w[0]; g_detmask[1] = w[1];
        g_detmask[2] = w[2]; g_detmask[3] = w[3];
        g_hasdet = (tot > 0) ? 1 : 0;
        g_alldet = (tot == 128) ? 1 : 0;
    }
}

// ---------------------------------------------------------------------------
// Packed f32x2 helpers
// ---------------------------------------------------------------------------
__device__ __forceinline__ ull f2x2_mul(ull a, ull b) {
    ull r; asm("mul.rn.f32x2 %0, %1, %2;" : "=l"(r) : "l"(a), "l"(b)); return r;
}
__device__ __forceinline__ ull f2x2_fma(ull a, ull b, ull c) {
    ull r; asm("fma.rn.f32x2 %0, %1, %2, %3;" : "=l"(r) : "l"(a), "l"(b), "l"(c)); return r;
}
__device__ __forceinline__ ull f2x2_pack(float lo, float hi) {
    ull r; asm("mov.b64 %0, {%1, %2};" : "=l"(r) : "f"(lo), "f"(hi)); return r;
}
__device__ __forceinline__ void f2x2_unpack(ull v, float& lo, float& hi) {
    asm("mov.b64 {%0, %1}, %2;" : "=f"(lo), "=f"(hi) : "l"(v));
}
#define EX2(dst, src) asm("ex2.approx.f32 %0, %1;" : "=f"(dst) : "f"(src))

// ---------------------------------------------------------------------------
// Phase B: grid (3, 641). Each block = one 256-pixel segment of one row.
// SMEM holds y-interpolated (log2e-prescaled) input columns (stride 132).
// Thread-per-pixel, fused single pass over 128 channels.
// Fast path (all slots detected): packed lerp, group-wise argmax, no bias.
// ---------------------------------------------------------------------------
#define NCOLS   65
#define STRIDE  132

__global__ void __launch_bounds__(256, 4)
postproc_kernel(const float* __restrict__ in, float* __restrict__ out) {
    __shared__ float sbuf[NCOLS * STRIDE];   // 34320 B
    __shared__ float sbias[128];
    __shared__ int   ssem[128];
    __shared__ int   smaskid[128];

    const int y  = blockIdx.y;
    const int y0 = y >> 2;
    const int y1 = min(y0 + 1, H_IN - 1);
    const float wy = (float)(y & 3) * 0.25f;
    const float w1 = wy * LOG2E;
    const float w0 = (1.0f - wy) * LOG2E;

    const int cb = blockIdx.x * 64;            // base input column: 0 / 64 / 128
    const int nc = min(NCOLS, W_IN - cb);      // 65 / 65 / 33

    // ---- fill: y-lerp (prescaled by log2e) into SMEM ----
    {
        const float4* r0 = (const float4*)(in + ((size_t)y0 * W_IN + cb) * C);
        const float4* r1 = (const float4*)(in + ((size_t)y1 * W_IN + cb) * C);
        const int nv = nc * 32;                // float4s
        for (int i = threadIdx.x; i < nv; i += 256) {
            const int col = i >> 5, j = i & 31;
            float4 a = r0[col * 32 + j];
            float4 b = r1[col * 32 + j];
            float4 t;
            t.x = a.x * w0 + b.x * w1;
            t.y = a.y * w0 + b.y * w1;
            t.z = a.z * w0 + b.z * w1;
            t.w = a.w * w0 + b.w * w1;
            *(float4*)(sbuf + col * STRIDE + j * 4) = t;
        }
        if (threadIdx.x < 128) {
            unsigned m = g_detmask[threadIdx.x >> 5];
            sbias[threadIdx.x] = ((m >> (threadIdx.x & 31)) & 1u) ? 0.0f : NEGV;
            ssem[threadIdx.x]    = g_sem[threadIdx.x];
            smaskid[threadIdx.x] = g_maskid[threadIdx.x];
        }
    }
    __syncthreads();

    const int px = cb * 4 + threadIdx.x;       // output x of this thread
    if (px >= W_OUT) return;

    const int x0 = px >> 2;
    const int x1 = min(x0 + 1, W_IN - 1);
    const float wx   = (float)(px & 3) * 0.25f;
    const float omwx = 1.0f - wx;

    const int hasdet = g_hasdet;

    float cf;       // confident_region value
    int   bi;       // argmax slot

    if (g_alldet) {
        // ---------------- FAST PATH: all slots detected ----------------
        // masked == resized, full_max == det_max, detected_pixel == 1.
        const ull* pa = (const ull*)(sbuf + (x0 - cb) * STRIDE);
        const ull* pb = (const ull*)(sbuf + (x1 - cb) * STRIDE);
        const ull wx2   = f2x2_pack(wx, wx);
        const ull omwx2 = f2x2_pack(omwx, omwx);

        float bv = -FLT_MAX;
        int   bg = 0;
        float s0 = 0.0f, s1 = 0.0f;

        #pragma unroll
        for (int g = 0; g < 32; ++g) {
            ull A01 = pa[2 * g];
            ull A23 = pa[2 * g + 1];
            ull B01 = pb[2 * g];
            ull B23 = pb[2 * g + 1];
            ull v01 = f2x2_fma(B01, wx2, f2x2_mul(A01, omwx2));
            ull v23 = f2x2_fma(B23, wx2, f2x2_mul(A23, omwx2));
            float v0, v1, v2, v3;
            f2x2_unpack(v01, v0, v1);
            f2x2_unpack(v23, v2, v3);
            float gm = fmaxf(fmaxf(v0, v1), fmaxf(v2, v3));
            bool t = (gm > bv);          // strict >: keeps earliest group on ties
            bv = t ? gm : bv;
            bg = t ? g  : bg;
            float e0, e1, e2, e3;
            EX2(e0, v0); EX2(e1, v1); EX2(e2, v2); EX2(e3, v3);
            s0 += e0; s1 += e1; s0 += e2; s1 += e3;
        }
        const float s = s0 + s1;

        // epilogue: recover within-group index (first occurrence, identical FP ops)
        {
            ull A01 = pa[2 * bg];
            ull A23 = pa[2 * bg + 1];
            ull B01 = pb[2 * bg];
            ull B23 = pb[2 * bg + 1];
            ull v01 = f2x2_fma(B01, wx2, f2x2_mul(A01, omwx2));
            ull v23 = f2x2_fma(B23, wx2, f2x2_mul(A23, omwx2));
            float v0, v1, v2, v3;
            f2x2_unpack(v01, v0, v1);
            f2x2_unpack(v23, v2, v3);
            int r = 3;
            if (v2 == bv) r = 2;
            if (v1 == bv) r = 1;
            if (v0 == bv) r = 0;
            bi = 4 * bg + r;
        }

        // pixel_conf > 0.4  <=>  s < 2.5 * 2^bv   (detected_pixel == 1)
        float eb; EX2(eb, bv);
        cf = (s < 2.5f * eb) ? 1.0f : 0.0f;
    } else {
        // ---------------- GENERAL PATH (bias-masked, proven) ----------------
        const float4* pa = (const float4*)(sbuf + (x0 - cb) * STRIDE);
        const float4* pb = (const float4*)(sbuf + (x1 - cb) * STRIDE);
        const float4* pg = (const float4*)sbias;

        float fm = -FLT_MAX;
        float bv = -FLT_MAX;
        float s  = 0.0f;
        bi = 0;

        #pragma unroll
        for (int c4 = 0; c4 < 32; ++c4) {
            const float4 A = pa[c4];
            const float4 B = pb[c4];
            const float4 G = pg[c4];
            {
                float v = A.x * omwx + B.x * wx;
                fm = fmaxf(fm, v);
                float mv = v + G.x;
                if (mv > bv) { bv = mv; bi = 4 * c4 + 0; }
                float e; EX2(e, mv); s += e;
            }
            {
                float v = A.y * omwx + B.y * wx;
                fm = fmaxf(fm, v);
                float mv = v + G.y;
                if (mv > bv) { bv = mv; bi = 4 * c4 + 1; }
                float e; EX2(e, mv); s += e;
            }
            {
                float v = A.z * omwx + B.z * wx;
                fm = fmaxf(fm, v);
                float mv = v + G.z;
                if (mv > bv) { bv = mv; bi = 4 * c4 + 2; }
                float e; EX2(e, mv); s += e;
            }
            {
                float v = A.w * omwx + B.w * wx;
                fm = fmaxf(fm, v);
                float mv = v + G.w;
                if (mv > bv) { bv = mv; bi = 4 * c4 + 3; }
                float e; EX2(e, mv); s += e;
            }
        }
        float eb; EX2(eb, bv);
        cf = (s < 2.5f * eb && fm == bv) ? 1.0f : 0.0f;
    }

    float maskid, sem, thing, stuff;
    if (hasdet) {
        const int semI = ssem[bi];
        maskid = (float)(smaskid[bi] + 1);
        sem    = (float)semI;                 // THING_STUFF_IDS == identity
        thing  = (semI < 80)  ? cf : 0.0f;
        stuff  = (semI >= 80) ? cf : 0.0f;
    } else {
        maskid = 1.0f; sem = 0.0f; thing = 0.0f; stuff = 0.0f;
    }

    const int p = y * W_OUT + px;
    out[p]            = maskid;
    out[NPIX + p]     = sem;
    out[2 * NPIX + p] = thing;
    out[3 * NPIX + p] = stuff;
}

// ---------------------------------------------------------------------------
extern "C" void kernel_launch(void* const* d_in, const int* in_sizes, int n_in,
                              void* d_out, int out_size) {
    const float* logits = (const float*)d_in[0];  // (161,161,128)
    const float* probs  = (const float*)d_in[1];  // (128,134)
    if (n_in >= 2 && in_sizes[0] < in_sizes[1]) { // safety: order by size
        const float* t = logits; logits = probs; probs = t;
    }
    float* out = (float*)d_out;

    classify_kernel<<<1, 128>>>(probs);
    postproc_kernel<<<dim3(3, H_OUT), 256>>>(logits, out);
}